// round 1
// baseline (speedup 1.0000x reference)
#include <cuda_runtime.h>
#include <cstdint>

#define BATCH 8
#define NPTS  8192
#define NS    2048          // S = 0.25 * N
#define KNBR  32
#define T1    1024
#define PPT   (NPTS / T1)   // 8 points per thread in FPS

// scratch: packed centroids (b, s, 3)
__device__ float g_new_xyz[BATCH * NS * 3];

// ---------------------------------------------------------------------------
// Kernel 1: farthest point sampling. One block per batch, 1024 threads.
// Points live in registers; smem holds a copy only for centroid lookup.
// Reproduces jnp.argmax first-occurrence tie-break (lowest index wins).
// ---------------------------------------------------------------------------
extern "C" __global__ __launch_bounds__(T1, 1)
void fps_kernel(const float* __restrict__ xyz, float* __restrict__ out)
{
    extern __shared__ float sm[];
    float* sx = sm;
    float* sy = sm + NPTS;
    float* sz = sm + 2 * NPTS;
    __shared__ float rv[32];
    __shared__ int   ri[32];
    __shared__ int   sFar;

    const int b = blockIdx.x;
    const int t = threadIdx.x;
    const int lane = t & 31;
    const int w    = t >> 5;

    const float* base = xyz + (size_t)b * NPTS * 3;

    float px[PPT], py[PPT], pz[PPT], dd[PPT];
#pragma unroll
    for (int i = 0; i < PPT; i++) {
        int idx = t + i * T1;
        float x = base[idx * 3 + 0];
        float y = base[idx * 3 + 1];
        float z = base[idx * 3 + 2];
        px[i] = x; py[i] = y; pz[i] = z;
        sx[idx] = x; sy[idx] = y; sz[idx] = z;
        dd[i] = 1e10f;
    }
    __syncthreads();

    int far = 0;
    float* out_xyz = out + (size_t)b * 3 * NS;

    for (int s = 0; s < NS; s++) {
        float cx = sx[far], cy = sy[far], cz = sz[far];
        if (t == 0) {
            out_xyz[0 * NS + s] = cx;
            out_xyz[1 * NS + s] = cy;
            out_xyz[2 * NS + s] = cz;
            float* g = g_new_xyz + (size_t)(b * NS + s) * 3;
            g[0] = cx; g[1] = cy; g[2] = cz;
        }

        float bv = -1.0f;
        int   bi = 0x7fffffff;
#pragma unroll
        for (int i = 0; i < PPT; i++) {
            // exact f32, no fma contraction, sum order (d0+d1)+d2
            float dx = __fsub_rn(px[i], cx);
            float dy = __fsub_rn(py[i], cy);
            float dz = __fsub_rn(pz[i], cz);
            float d  = __fadd_rn(__fadd_rn(__fmul_rn(dx, dx), __fmul_rn(dy, dy)),
                                 __fmul_rn(dz, dz));
            float nd = fminf(dd[i], d);
            dd[i] = nd;
            int idx = t + i * T1;
            if (nd > bv || (nd == bv && idx < bi)) { bv = nd; bi = idx; }
        }
        // warp argmax (lowest index on ties)
#pragma unroll
        for (int off = 16; off; off >>= 1) {
            float ov = __shfl_xor_sync(0xffffffffu, bv, off);
            int   oi = __shfl_xor_sync(0xffffffffu, bi, off);
            if (ov > bv || (ov == bv && oi < bi)) { bv = ov; bi = oi; }
        }
        if (lane == 0) { rv[w] = bv; ri[w] = bi; }
        __syncthreads();
        if (w == 0) {
            bv = rv[lane]; bi = ri[lane];
#pragma unroll
            for (int off = 16; off; off >>= 1) {
                float ov = __shfl_xor_sync(0xffffffffu, bv, off);
                int   oi = __shfl_xor_sync(0xffffffffu, bi, off);
                if (ov > bv || (ov == bv && oi < bi)) { bv = ov; bi = oi; }
            }
            if (lane == 0) sFar = bi;
        }
        __syncthreads();
        far = sFar;
    }
}

// ---------------------------------------------------------------------------
// Kernel 2: fused ball query + grouping + 3-layer pointwise MLP + max pool.
// One warp per centroid; 8 warps / 256-thread block. Weights in SMEM.
// ---------------------------------------------------------------------------
extern "C" __global__ __launch_bounds__(256)
void group_mlp_kernel(const float* __restrict__ xyz,
                      const float* __restrict__ w1, const float* __restrict__ b1,
                      const float* __restrict__ w2, const float* __restrict__ b2,
                      const float* __restrict__ w3, const float* __restrict__ b3,
                      float* __restrict__ out_pts)
{
    extern __shared__ float sm[];
    float* w1s = sm;              // 64x3
    float* b1s = w1s + 192;       // 64
    float* w2t = b1s + 64;        // 64x64 transposed: [c][o]
    float* b2s = w2t + 4096;      // 64
    float* w3s = b2s + 64;        // 128x64 row-major [o][c]
    float* b3s = w3s + 8192;      // 128
    int*   lists = (int*)(b3s + 128);  // 8 warps * 32

    const int t = threadIdx.x;
    for (int i = t; i < 192; i += 256) w1s[i] = w1[i];
    if (t < 64) { b1s[t] = b1[t]; b2s[t] = b2[t]; }
    for (int i = t; i < 4096; i += 256) {
        int o = i >> 6, c = i & 63;
        w2t[c * 64 + o] = w2[i];
    }
    for (int i = t; i < 8192; i += 256) w3s[i] = w3[i];
    if (t < 128) b3s[t] = b3[t];
    __syncthreads();

    const int w    = t >> 5;
    const int lane = t & 31;
    const int g    = blockIdx.x * 8 + w;      // 0 .. B*NS-1
    const int b    = g / NS;
    const int s    = g - b * NS;

    const float* xb   = xyz + (size_t)b * NPTS * 3;
    const float* cptr = g_new_xyz + (size_t)(b * NS + s) * 3;
    const float cx = cptr[0], cy = cptr[1], cz = cptr[2];

    // --- ball query: first KNBR points (ascending index) with d2 <= 0.04 ---
    int* list = lists + w * KNBR;
    int  cnt  = 0;
    for (int basei = 0; basei < NPTS; basei += 32) {
        int idx = basei + lane;
        float x = xb[idx * 3 + 0];
        float y = xb[idx * 3 + 1];
        float z = xb[idx * 3 + 2];
        float dx = __fsub_rn(x, cx);
        float dy = __fsub_rn(y, cy);
        float dz = __fsub_rn(z, cz);
        float d  = __fadd_rn(__fadd_rn(__fmul_rn(dx, dx), __fmul_rn(dy, dy)),
                             __fmul_rn(dz, dz));
        bool within = (d <= 0.04f);
        unsigned m  = __ballot_sync(0xffffffffu, within);
        if (within) {
            int pos = cnt + __popc(m & ((1u << lane) - 1u));
            if (pos < KNBR) list[pos] = idx;
        }
        cnt += __popc(m);
        if (cnt >= KNBR) break;
    }
    __syncwarp();
    const int nb = list[(lane < cnt) ? lane : 0];

    // --- grouping: relative coords for this lane's neighbor ---
    const float rx = xb[nb * 3 + 0] - cx;
    const float ry = xb[nb * 3 + 1] - cy;
    const float rz = xb[nb * 3 + 2] - cz;

    // --- layer 1 fused into layer 2 accumulation (only h2 kept live) ---
    float h2[64];
#pragma unroll
    for (int o = 0; o < 64; o++) h2[o] = b2s[o];

    for (int c = 0; c < 64; c++) {
        float a = fmaf(rx, w1s[c * 3 + 0], b1s[c]);
        a = fmaf(ry, w1s[c * 3 + 1], a);
        a = fmaf(rz, w1s[c * 3 + 2], a);
        float hv = fmaxf(a, 0.0f);
        const float4* row = (const float4*)(w2t + c * 64);
#pragma unroll
        for (int o4 = 0; o4 < 16; o4++) {
            float4 wv = row[o4];
            h2[o4 * 4 + 0] = fmaf(hv, wv.x, h2[o4 * 4 + 0]);
            h2[o4 * 4 + 1] = fmaf(hv, wv.y, h2[o4 * 4 + 1]);
            h2[o4 * 4 + 2] = fmaf(hv, wv.z, h2[o4 * 4 + 2]);
            h2[o4 * 4 + 3] = fmaf(hv, wv.w, h2[o4 * 4 + 3]);
        }
    }
#pragma unroll
    for (int o = 0; o < 64; o++) h2[o] = fmaxf(h2[o], 0.0f);

    // --- layer 3 + relu + warp max-pool over 32 neighbors ---
    float* outb = out_pts + (size_t)b * 128 * NS + s;
    for (int o = 0; o < 128; o++) {
        float a = b3s[o];
        const float4* row = (const float4*)(w3s + o * 64);
#pragma unroll
        for (int c4 = 0; c4 < 16; c4++) {
            float4 wv = row[c4];
            a = fmaf(h2[c4 * 4 + 0], wv.x, a);
            a = fmaf(h2[c4 * 4 + 1], wv.y, a);
            a = fmaf(h2[c4 * 4 + 2], wv.z, a);
            a = fmaf(h2[c4 * 4 + 3], wv.w, a);
        }
        a = fmaxf(a, 0.0f);
#pragma unroll
        for (int off = 16; off; off >>= 1)
            a = fmaxf(a, __shfl_xor_sync(0xffffffffu, a, off));
        if (lane == 0) outb[(size_t)o * NS] = a;
    }
}

// ---------------------------------------------------------------------------
extern "C" void kernel_launch(void* const* d_in, const int* in_sizes, int n_in,
                              void* d_out, int out_size)
{
    const float* xyz = (const float*)d_in[0];
    // d_in[1] = features (unused by the reference computation)
    const float* w1 = (const float*)d_in[2];
    const float* b1 = (const float*)d_in[3];
    const float* w2 = (const float*)d_in[4];
    const float* b2 = (const float*)d_in[5];
    const float* w3 = (const float*)d_in[6];
    const float* b3 = (const float*)d_in[7];

    float* out = (float*)d_out;
    float* out_pts = out + (size_t)BATCH * 3 * NS;   // new_points after new_xyz

    const int fps_smem = 3 * NPTS * sizeof(float);                 // 96 KB
    const int mlp_smem = (192 + 64 + 4096 + 64 + 8192 + 128) * 4
                       + 8 * KNBR * (int)sizeof(int);              // ~51 KB

    cudaFuncSetAttribute(fps_kernel,
                         cudaFuncAttributeMaxDynamicSharedMemorySize, fps_smem);
    cudaFuncSetAttribute(group_mlp_kernel,
                         cudaFuncAttributeMaxDynamicSharedMemorySize, mlp_smem);

    fps_kernel<<<BATCH, T1, fps_smem>>>(xyz, out);
    group_mlp_kernel<<<(BATCH * NS) / 8, 256, mlp_smem>>>(
        xyz, w1, b1, w2, b2, w3, b3, out_pts);
}

// round 2
// speedup vs baseline: 1.0833x; 1.0833x over previous
#include <cuda_runtime.h>
#include <cstdint>

#define BATCH 8
#define NPTS  8192
#define NS    2048
#define KNBR  32
#define TB    512
#define PPT   (NPTS / TB)    // 16 points per thread in FPS
#define NWARP (TB / 32)      // 16

// scratch
__device__ float    g_new_xyz[BATCH * NS * 3];
__device__ unsigned g_progress[BATCH];

__device__ __forceinline__ unsigned ld_acq(const unsigned* p) {
    unsigned v;
    asm volatile("ld.acquire.gpu.global.u32 %0, [%1];" : "=r"(v) : "l"(p) : "memory");
    return v;
}
__device__ __forceinline__ void st_rel(unsigned* p, unsigned v) {
    asm volatile("st.release.gpu.global.u32 [%0], %1;" :: "l"(p), "r"(v) : "memory");
}

extern "C" __global__ void reset_kernel() {
    if (threadIdx.x < BATCH) g_progress[threadIdx.x] = 0;
}

// ---------------------------------------------------------------------------
// Fused kernel. Blocks 0..7: FPS producer (one per batch).
// Blocks 8..: warp-per-centroid ball query + MLP + max pool, gated on
// the per-batch progress counter.
// ---------------------------------------------------------------------------
extern "C" __global__ void __launch_bounds__(TB, 1)
fused_kernel(const float* __restrict__ xyz,
             const float* __restrict__ w1, const float* __restrict__ b1,
             const float* __restrict__ w2, const float* __restrict__ b2,
             const float* __restrict__ w3, const float* __restrict__ b3,
             float* __restrict__ out)
{
    extern __shared__ float sm[];
    const int t    = threadIdx.x;
    const int lane = t & 31;
    const int w    = t >> 5;

    if (blockIdx.x < BATCH) {
        // ================= FPS producer =================
        __shared__ int sval[2][NWARP];
        __shared__ int sidx[2][NWARP];
        float* sx = sm;
        float* sy = sm + NPTS;
        float* sz = sm + 2 * NPTS;

        const int b = blockIdx.x;
        const float* base = xyz + (size_t)b * NPTS * 3;

        float px[PPT], py[PPT], pz[PPT], dd[PPT];
#pragma unroll
        for (int i = 0; i < PPT; i++) {
            int idx = t + i * TB;
            float x = base[idx * 3 + 0];
            float y = base[idx * 3 + 1];
            float z = base[idx * 3 + 2];
            px[i] = x; py[i] = y; pz[i] = z;
            sx[idx] = x; sy[idx] = y; sz[idx] = z;
            dd[i] = 1e10f;
        }
        __syncthreads();

        int far = 0;
        float* out_xyz = out + (size_t)b * 3 * NS;
        float* gx      = g_new_xyz + (size_t)b * NS * 3;

        for (int s = 0; s < NS; s++) {
            float cx = sx[far], cy = sy[far], cz = sz[far];
            if (t == 0) {
                out_xyz[0 * NS + s] = cx;
                out_xyz[1 * NS + s] = cy;
                out_xyz[2 * NS + s] = cz;
                gx[s * 3 + 0] = cx; gx[s * 3 + 1] = cy; gx[s * 3 + 2] = cz;
                st_rel(&g_progress[b], (unsigned)(s + 1));
            }

            float bv = -1.0f;
            int   bi = 0x7fffffff;
#pragma unroll
            for (int i = 0; i < PPT; i++) {
                // exact f32, no fma contraction, sum order (d0+d1)+d2
                float dx = __fsub_rn(px[i], cx);
                float dy = __fsub_rn(py[i], cy);
                float dz = __fsub_rn(pz[i], cz);
                float d  = __fadd_rn(__fadd_rn(__fmul_rn(dx, dx), __fmul_rn(dy, dy)),
                                     __fmul_rn(dz, dz));
                float nd = fminf(dd[i], d);
                dd[i] = nd;
                // ascending idx within thread: strict > keeps lowest index on ties
                if (nd > bv) { bv = nd; bi = t + i * TB; }
            }
            // warp argmax via REDUX (exact lowest-index tie-break)
            int fb = __float_as_int(bv);                 // bv >= -1; values >=0 dominate
            int mb = __reduce_max_sync(0xffffffffu, fb);
            int ca = (fb == mb) ? bi : 0x7fffffff;
            int wi = __reduce_min_sync(0xffffffffu, ca);
            if (lane == 0) { sval[s & 1][w] = mb; sidx[s & 1][w] = wi; }
            __syncthreads();
            // every warp combines the 16 per-warp winners (no 2nd barrier)
            int vv = (lane < NWARP) ? sval[s & 1][lane] : (int)0x80000000;
            int ii = (lane < NWARP) ? sidx[s & 1][lane] : 0x7fffffff;
            int m2 = __reduce_max_sync(0xffffffffu, vv);
            int c2 = (vv == m2) ? ii : 0x7fffffff;
            far = __reduce_min_sync(0xffffffffu, c2);
        }
    } else {
        // ================= MLP consumer =================
        float* w1s = sm;              // 64x3
        float* b1s = w1s + 192;       // 64
        float* w2t = b1s + 64;        // 64x64 transposed [c][o]
        float* b2s = w2t + 4096;      // 64
        float* w3s = b2s + 64;        // 128x64 row-major [o][c]
        float* b3s = w3s + 8192;      // 128
        int*   lists = (int*)(b3s + 128);  // NWARP * 32

        for (int i = t; i < 192; i += TB) w1s[i] = w1[i];
        if (t < 64) { b1s[t] = b1[t]; b2s[t] = b2[t]; }
        for (int i = t; i < 4096; i += TB) {
            int o = i >> 6, c = i & 63;
            w2t[c * 64 + o] = w2[i];
        }
        for (int i = t; i < 8192; i += TB) w3s[i] = w3[i];
        if (t < 128) b3s[t] = b3[t];
        __syncthreads();

        const int g = (blockIdx.x - BATCH) * NWARP + w;  // 0 .. B*NS-1
        const int b = g & 7;
        const int s = g >> 3;

        // wait for centroid s of batch b
        unsigned need = (unsigned)(s + 1);
        while (ld_acq(&g_progress[b]) < need) __nanosleep(256);

        const float* xb   = xyz + (size_t)b * NPTS * 3;
        const float* cptr = g_new_xyz + ((size_t)b * NS + s) * 3;
        const float cx = cptr[0], cy = cptr[1], cz = cptr[2];

        // --- ball query: first KNBR points (ascending idx) with d2 <= r^2 ---
        int* list = lists + w * KNBR;
        int  cnt  = 0;
        for (int basei = 0; basei < NPTS; basei += 32) {
            int idx = basei + lane;
            float x = xb[idx * 3 + 0];
            float y = xb[idx * 3 + 1];
            float z = xb[idx * 3 + 2];
            float dx = __fsub_rn(x, cx);
            float dy = __fsub_rn(y, cy);
            float dz = __fsub_rn(z, cz);
            float d  = __fadd_rn(__fadd_rn(__fmul_rn(dx, dx), __fmul_rn(dy, dy)),
                                 __fmul_rn(dz, dz));
            bool within = (d <= 0.04f);
            unsigned m  = __ballot_sync(0xffffffffu, within);
            if (within) {
                int pos = cnt + __popc(m & ((1u << lane) - 1u));
                if (pos < KNBR) list[pos] = idx;
            }
            cnt += __popc(m);
            if (cnt >= KNBR) break;
        }
        __syncwarp();
        const int nb = list[(lane < cnt) ? lane : 0];

        const float rx = xb[nb * 3 + 0] - cx;
        const float ry = xb[nb * 3 + 1] - cy;
        const float rz = xb[nb * 3 + 2] - cz;

        // --- layer1 fused into layer2 accumulation ---
        float h2[64];
#pragma unroll
        for (int o = 0; o < 64; o++) h2[o] = b2s[o];

        for (int c = 0; c < 64; c++) {
            float a = fmaf(rx, w1s[c * 3 + 0], b1s[c]);
            a = fmaf(ry, w1s[c * 3 + 1], a);
            a = fmaf(rz, w1s[c * 3 + 2], a);
            float hv = fmaxf(a, 0.0f);
            const float4* row = (const float4*)(w2t + c * 64);
#pragma unroll
            for (int o4 = 0; o4 < 16; o4++) {
                float4 wv = row[o4];
                h2[o4 * 4 + 0] = fmaf(hv, wv.x, h2[o4 * 4 + 0]);
                h2[o4 * 4 + 1] = fmaf(hv, wv.y, h2[o4 * 4 + 1]);
                h2[o4 * 4 + 2] = fmaf(hv, wv.z, h2[o4 * 4 + 2]);
                h2[o4 * 4 + 3] = fmaf(hv, wv.w, h2[o4 * 4 + 3]);
            }
        }
#pragma unroll
        for (int o = 0; o < 64; o++) h2[o] = fmaxf(h2[o], 0.0f);

        // --- layer3 + relu + warp max-pool ---
        float* outb = out + (size_t)BATCH * 3 * NS + (size_t)b * 128 * NS + s;
        for (int o = 0; o < 128; o++) {
            float a = b3s[o];
            const float4* row = (const float4*)(w3s + o * 64);
#pragma unroll
            for (int c4 = 0; c4 < 16; c4++) {
                float4 wv = row[c4];
                a = fmaf(h2[c4 * 4 + 0], wv.x, a);
                a = fmaf(h2[c4 * 4 + 1], wv.y, a);
                a = fmaf(h2[c4 * 4 + 2], wv.z, a);
                a = fmaf(h2[c4 * 4 + 3], wv.w, a);
            }
            a = fmaxf(a, 0.0f);
#pragma unroll
            for (int off = 16; off; off >>= 1)
                a = fmaxf(a, __shfl_xor_sync(0xffffffffu, a, off));
            if (lane == 0) outb[(size_t)o * NS] = a;
        }
    }
}

// ---------------------------------------------------------------------------
extern "C" void kernel_launch(void* const* d_in, const int* in_sizes, int n_in,
                              void* d_out, int out_size)
{
    const float* xyz = (const float*)d_in[0];
    const float* w1 = (const float*)d_in[2];
    const float* b1 = (const float*)d_in[3];
    const float* w2 = (const float*)d_in[4];
    const float* b2 = (const float*)d_in[5];
    const float* w3 = (const float*)d_in[6];
    const float* b3 = (const float*)d_in[7];

    float* out = (float*)d_out;

    const int smem = 3 * NPTS * sizeof(float);   // 96 KB (covers MLP's ~53 KB too)
    cudaFuncSetAttribute(fused_kernel,
                         cudaFuncAttributeMaxDynamicSharedMemorySize, smem);

    const int nmlp = (BATCH * NS) / NWARP;       // 1024 consumer blocks
    reset_kernel<<<1, 32>>>();
    fused_kernel<<<BATCH + nmlp, TB, smem>>>(xyz, w1, b1, w2, b2, w3, b3, out);
}

// round 3
// speedup vs baseline: 2.2461x; 2.0734x over previous
#include <cuda_runtime.h>
#include <cstdint>

#define BATCH 8
#define NPTS  8192
#define NS    2048
#define KNBR  32
#define TB    512
#define PPT   (NPTS / TB)    // 16 points per thread in FPS
#define NPAIR (PPT / 2)      // 8 packed pairs
#define NWARP (TB / 32)      // 16

// scratch
__device__ float    g_new_xyz[BATCH * NS * 3];
__device__ unsigned g_progress[BATCH];

__device__ __forceinline__ unsigned ld_acq(const unsigned* p) {
    unsigned v;
    asm volatile("ld.acquire.gpu.global.u32 %0, [%1];" : "=r"(v) : "l"(p) : "memory");
    return v;
}
__device__ __forceinline__ void st_rel(unsigned* p, unsigned v) {
    asm volatile("st.release.gpu.global.u32 [%0], %1;" :: "l"(p), "r"(v) : "memory");
}

// packed f32x2 helpers (two independent IEEE f32 ops per instruction)
__device__ __forceinline__ unsigned long long pk2(float lo, float hi) {
    unsigned long long r;
    asm("mov.b64 %0, {%1, %2};" : "=l"(r) : "f"(lo), "f"(hi));
    return r;
}
__device__ __forceinline__ void upk2(float& lo, float& hi, unsigned long long v) {
    asm("mov.b64 {%0, %1}, %2;" : "=f"(lo), "=f"(hi) : "l"(v));
}
__device__ __forceinline__ unsigned long long add2(unsigned long long a, unsigned long long b) {
    unsigned long long r;
    asm("add.rn.f32x2 %0, %1, %2;" : "=l"(r) : "l"(a), "l"(b));
    return r;
}
__device__ __forceinline__ unsigned long long mul2(unsigned long long a, unsigned long long b) {
    unsigned long long r;
    asm("mul.rn.f32x2 %0, %1, %2;" : "=l"(r) : "l"(a), "l"(b));
    return r;
}

extern "C" __global__ void reset_kernel() {
    if (threadIdx.x < BATCH) g_progress[threadIdx.x] = 0;
}

// ---------------------------------------------------------------------------
// Fused kernel. Blocks 0..7: FPS producer (one per batch).
// Blocks 8..: 16 warps, each handling one centroid: ball query + MLP + pool.
// ---------------------------------------------------------------------------
extern "C" __global__ void __launch_bounds__(TB, 1)
fused_kernel(const float* __restrict__ xyz,
             const float* __restrict__ w1, const float* __restrict__ b1,
             const float* __restrict__ w2, const float* __restrict__ b2,
             const float* __restrict__ w3, const float* __restrict__ b3,
             float* __restrict__ out)
{
    extern __shared__ float sm[];
    const int t    = threadIdx.x;
    const int lane = t & 31;
    const int w    = t >> 5;

    if (blockIdx.x < BATCH) {
        // ================= FPS producer =================
        __shared__ int sval[2][NWARP];
        __shared__ int sidx[2][NWARP];
        float* sx = sm;
        float* sy = sm + NPTS;
        float* sz = sm + 2 * NPTS;

        const int b = blockIdx.x;
        const float* base = xyz + (size_t)b * NPTS * 3;

        // pair p holds points idx = t + (2p)*TB (lo) and t + (2p+1)*TB (hi)
        unsigned long long px2[NPAIR], py2[NPAIR], pz2[NPAIR];
        float dd[PPT];
#pragma unroll
        for (int i = 0; i < PPT; i++) {
            int idx = t + i * TB;
            float x = base[idx * 3 + 0];
            float y = base[idx * 3 + 1];
            float z = base[idx * 3 + 2];
            sx[idx] = x; sy[idx] = y; sz[idx] = z;
            dd[i] = 1e10f;
            if (i & 1) {
                float xl, yl, zl;
                upk2(xl, yl, px2[i >> 1]);  // temporarily holds (x_lo in lo)
                (void)yl; (void)zl;
            }
        }
        // build packed pairs (separate pass keeps the load loop simple)
#pragma unroll
        for (int p = 0; p < NPAIR; p++) {
            int i0 = t + (2 * p) * TB;
            int i1 = t + (2 * p + 1) * TB;
            px2[p] = pk2(sx[i0], sx[i1]);
            py2[p] = pk2(sy[i0], sy[i1]);
            pz2[p] = pk2(sz[i0], sz[i1]);
        }
        __syncthreads();

        int far = 0;
        float* out_xyz = out + (size_t)b * 3 * NS;
        float* gx      = g_new_xyz + (size_t)b * NS * 3;

        for (int s = 0; s < NS; s++) {
            float cx = sx[far], cy = sy[far], cz = sz[far];
            if (t == 0) {
                out_xyz[0 * NS + s] = cx;
                out_xyz[1 * NS + s] = cy;
                out_xyz[2 * NS + s] = cz;
                gx[s * 3 + 0] = cx; gx[s * 3 + 1] = cy; gx[s * 3 + 2] = cz;
                if ((s & 15) == 15) st_rel(&g_progress[b], (unsigned)(s + 1));
            }
            // negation is exact; a + (-c) == a - c in IEEE
            unsigned long long ncx = pk2(-cx, -cx);
            unsigned long long ncy = pk2(-cy, -cy);
            unsigned long long ncz = pk2(-cz, -cz);

            float bv = -1.0f;
            int   bi = 0x7fffffff;
#pragma unroll
            for (int p = 0; p < NPAIR; p++) {
                unsigned long long dx = add2(px2[p], ncx);
                unsigned long long dy = add2(py2[p], ncy);
                unsigned long long dz = add2(pz2[p], ncz);
                dx = mul2(dx, dx);
                dy = mul2(dy, dy);
                dz = mul2(dz, dz);
                unsigned long long d2 = add2(add2(dx, dy), dz);   // (x2+y2)+z2
                float dlo, dhi;
                upk2(dlo, dhi, d2);
                float n0 = fminf(dd[2 * p + 0], dlo); dd[2 * p + 0] = n0;
                float n1 = fminf(dd[2 * p + 1], dhi); dd[2 * p + 1] = n1;
                // ascending idx within thread: strict > keeps lowest index on ties
                if (n0 > bv) { bv = n0; bi = t + (2 * p) * TB; }
                if (n1 > bv) { bv = n1; bi = t + (2 * p + 1) * TB; }
            }
            // warp argmax via REDUX (exact lowest-index tie-break)
            int fb = __float_as_int(bv);
            int mb = __reduce_max_sync(0xffffffffu, fb);
            int ca = (fb == mb) ? bi : 0x7fffffff;
            int wi = __reduce_min_sync(0xffffffffu, ca);
            if (lane == 0) { sval[s & 1][w] = mb; sidx[s & 1][w] = wi; }
            __syncthreads();
            int vv = (lane < NWARP) ? sval[s & 1][lane] : (int)0x80000000;
            int ii = (lane < NWARP) ? sidx[s & 1][lane] : 0x7fffffff;
            int m2 = __reduce_max_sync(0xffffffffu, vv);
            int c2 = (vv == m2) ? ii : 0x7fffffff;
            far = __reduce_min_sync(0xffffffffu, c2);
        }
        if (t == 0) st_rel(&g_progress[b], (unsigned)NS);
    } else {
        // ================= MLP consumer =================
        float* w1s = sm;              // 64x3
        float* b1s = w1s + 192;       // 64
        float* w2t = b1s + 64;        // 64x64 transposed [c][o]
        float* b2s = w2t + 4096;      // 64
        float* w3s = b2s + 64;        // 128x64 row-major [o][c]
        float* b3s = w3s + 8192;      // 128
        int*   lists = (int*)(b3s + 128);  // NWARP * 32

        for (int i = t; i < 192; i += TB) w1s[i] = w1[i];
        if (t < 64) { b1s[t] = b1[t]; b2s[t] = b2[t]; }
        for (int i = t; i < 4096; i += TB) {
            int o = i >> 6, c = i & 63;
            w2t[c * 64 + o] = w2[i];
        }
        for (int i = t; i < 8192; i += TB) w3s[i] = w3[i];
        if (t < 128) b3s[t] = b3[t];

        // block mapping: batch b, s range [sbase, sbase+16)
        const int idx  = blockIdx.x - BATCH;       // 0..1023
        const int b    = idx & 7;
        const int sbase = (idx >> 3) * NWARP;
        const int s    = sbase + w;

        // single poller per block, coarse gate on the whole block's range
        if (t == 0) {
            unsigned need = (unsigned)(sbase + NWARP);
            while (ld_acq(&g_progress[b]) < need) __nanosleep(2048);
        }
        __syncthreads();

        const float* xb   = xyz + (size_t)b * NPTS * 3;
        const float* cptr = g_new_xyz + ((size_t)b * NS + s) * 3;
        const float cx = cptr[0], cy = cptr[1], cz = cptr[2];

        // --- ball query: first KNBR points (ascending idx) with d2 <= r^2 ---
        int* list = lists + w * KNBR;
        int  cnt  = 0;
        for (int basei = 0; basei < NPTS; basei += 32) {
            int pi = basei + lane;
            float x = xb[pi * 3 + 0];
            float y = xb[pi * 3 + 1];
            float z = xb[pi * 3 + 2];
            float dx = __fsub_rn(x, cx);
            float dy = __fsub_rn(y, cy);
            float dz = __fsub_rn(z, cz);
            float d  = __fadd_rn(__fadd_rn(__fmul_rn(dx, dx), __fmul_rn(dy, dy)),
                                 __fmul_rn(dz, dz));
            bool within = (d <= 0.04f);
            unsigned m  = __ballot_sync(0xffffffffu, within);
            if (within) {
                int pos = cnt + __popc(m & ((1u << lane) - 1u));
                if (pos < KNBR) list[pos] = pi;
            }
            cnt += __popc(m);
            if (cnt >= KNBR) break;
        }
        __syncwarp();
        const int nb = list[(lane < cnt) ? lane : 0];

        const float rx = xb[nb * 3 + 0] - cx;
        const float ry = xb[nb * 3 + 1] - cy;
        const float rz = xb[nb * 3 + 2] - cz;

        // --- layer1 fused into layer2 accumulation ---
        float h2[64];
#pragma unroll
        for (int o = 0; o < 64; o++) h2[o] = b2s[o];

        for (int c = 0; c < 64; c++) {
            float a = fmaf(rx, w1s[c * 3 + 0], b1s[c]);
            a = fmaf(ry, w1s[c * 3 + 1], a);
            a = fmaf(rz, w1s[c * 3 + 2], a);
            float hv = fmaxf(a, 0.0f);
            const float4* row = (const float4*)(w2t + c * 64);
#pragma unroll
            for (int o4 = 0; o4 < 16; o4++) {
                float4 wv = row[o4];
                h2[o4 * 4 + 0] = fmaf(hv, wv.x, h2[o4 * 4 + 0]);
                h2[o4 * 4 + 1] = fmaf(hv, wv.y, h2[o4 * 4 + 1]);
                h2[o4 * 4 + 2] = fmaf(hv, wv.z, h2[o4 * 4 + 2]);
                h2[o4 * 4 + 3] = fmaf(hv, wv.w, h2[o4 * 4 + 3]);
            }
        }
#pragma unroll
        for (int o = 0; o < 64; o++) h2[o] = fmaxf(h2[o], 0.0f);

        // --- layer3 + relu + warp max-pool ---
        float* outb = out + (size_t)BATCH * 3 * NS + (size_t)b * 128 * NS + s;
        for (int o = 0; o < 128; o++) {
            float a = b3s[o];
            const float4* row = (const float4*)(w3s + o * 64);
#pragma unroll
            for (int c4 = 0; c4 < 16; c4++) {
                float4 wv = row[c4];
                a = fmaf(h2[c4 * 4 + 0], wv.x, a);
                a = fmaf(h2[c4 * 4 + 1], wv.y, a);
                a = fmaf(h2[c4 * 4 + 2], wv.z, a);
                a = fmaf(h2[c4 * 4 + 3], wv.w, a);
            }
            a = fmaxf(a, 0.0f);
#pragma unroll
            for (int off = 16; off; off >>= 1)
                a = fmaxf(a, __shfl_xor_sync(0xffffffffu, a, off));
            if (lane == 0) outb[(size_t)o * NS] = a;
        }
    }
}

// ---------------------------------------------------------------------------
extern "C" void kernel_launch(void* const* d_in, const int* in_sizes, int n_in,
                              void* d_out, int out_size)
{
    const float* xyz = (const float*)d_in[0];
    const float* w1 = (const float*)d_in[2];
    const float* b1 = (const float*)d_in[3];
    const float* w2 = (const float*)d_in[4];
    const float* b2 = (const float*)d_in[5];
    const float* w3 = (const float*)d_in[6];
    const float* b3 = (const float*)d_in[7];

    float* out = (float*)d_out;

    const int smem = 3 * NPTS * sizeof(float);   // 96 KB
    cudaFuncSetAttribute(fused_kernel,
                         cudaFuncAttributeMaxDynamicSharedMemorySize, smem);

    const int nmlp = (BATCH * NS) / NWARP;       // 1024 consumer blocks
    reset_kernel<<<1, 32>>>();
    fused_kernel<<<BATCH + nmlp, TB, smem>>>(xyz, w1, b1, w2, b2, w3, b3, out);
}